// round 3
// baseline (speedup 1.0000x reference)
#include <cuda_runtime.h>
#include <cuda_bf16.h>
#include <math.h>

#define SS   128
#define BB   32
#define NINP 1024
#define NHID 1024
#define NH   16
#define HDIM 64
#define VV   32000
#define NBLK 148

// ---------------- scratch (device globals; no allocation) ----------------
__device__ float g_emb[SS * BB * NINP];
__device__ float g_keys[(SS + 1) * BB * NHID];
__device__ float g_vals[(SS + 1) * BB * NHID];
__device__ float g_hidden[BB * NHID];
__device__ float g_q[BB * NHID];
__device__ float g_attn[BB * NHID];
__device__ float g_inter[BB * 4096];
__device__ float g_part[32 * BB * 1024];       // max over phases: KS*B*N = 1,048,576 floats (4 MB)
__device__ unsigned g_cnt;
__device__ unsigned g_gen;

// ---------------- grid barrier (persistent kernel) ----------------
__device__ __forceinline__ void gridbar() {
    __syncthreads();
    if (threadIdx.x == 0) {
        volatile unsigned* gen = &g_gen;
        unsigned g = *gen;
        __threadfence();
        if (atomicAdd(&g_cnt, 1u) == NBLK - 1) {
            g_cnt = 0;
            __threadfence();
            *gen = g + 1;
        } else {
            while (*gen == g) { }
        }
        __threadfence();   // gpu-scope fence (invalidate stale L1 lines)
    }
    __syncthreads();
}

// ---------------- shared memory union ----------------
union Smem {
    struct { float Xs[32][36]; float Ws[32][264]; } g;                 // 38400 B
    struct { float buf[4096]; float red[32]; float qs[1024]; float sc[16][132]; } l;
};

__device__ __forceinline__ float block_reduce(float v, float* red) {
    __syncthreads();
    int tid = threadIdx.x;
    #pragma unroll
    for (int o = 16; o > 0; o >>= 1) v += __shfl_xor_sync(~0u, v, o);
    if ((tid & 31) == 0) red[tid >> 5] = v;
    __syncthreads();
    if (tid < 8) {
        v = red[tid];
        #pragma unroll
        for (int o = 4; o > 0; o >>= 1) v += __shfl_xor_sync(0xff, v, o);
        if (tid == 0) red[0] = v;
    }
    __syncthreads();
    return red[0];
}

// ---------------- register-blocked GEMM phase ----------------
// out_part[ks][m][N] = X[32 x K] @ W[N x K]^T over k-chunk ks.
// Tile: 32m x 256n, 256 threads, 8m x 4n per thread.
// X addressed piecewise via segs[] with 2^segshift-sized segments, row stride xstride.
__device__ void gemm_phase(Smem& sm, const float* const* segs, int segshift, int xstride,
                           const float* __restrict__ W, int N, int K, int KS) {
    const int nTiles = N >> 8;
    const int ntasks = nTiles * KS;
    const int Kc = K / KS;
    const int tid = threadIdx.x;
    const int col = tid & 63;
    const int mg  = tid >> 6;
    const int lm  = tid >> 3;          // 0..31 (m or n row for loads)
    const int lk  = (tid & 7) * 4;     // k offset (float4)
    const unsigned kmask = (1u << segshift) - 1u;

    for (int task = blockIdx.x; task < ntasks; task += NBLK) {
        int nt = task / KS, ks = task - nt * KS;
        int n0 = nt << 8;
        int k0b = ks * Kc;
        float4 acc[8];
        #pragma unroll
        for (int i2 = 0; i2 < 8; i2++) acc[i2] = make_float4(0.f, 0.f, 0.f, 0.f);

        for (int k0 = k0b; k0 < k0b + Kc; k0 += 32) {
            const float* xseg = segs[k0 >> segshift];
            int koff = (k0 & kmask) + lk;
            // X tile: 32m x 32k -> Xs[k][m]
            {
                float4 v = *(const float4*)(xseg + (size_t)lm * xstride + koff);
                sm.g.Xs[lk + 0][lm] = v.x; sm.g.Xs[lk + 1][lm] = v.y;
                sm.g.Xs[lk + 2][lm] = v.z; sm.g.Xs[lk + 3][lm] = v.w;
            }
            // W tile: 256n x 32k -> Ws[k][n]
            #pragma unroll
            for (int r = 0; r < 8; r++) {
                int n = (r << 5) + lm;
                float4 v = *(const float4*)&W[(size_t)(n0 + n) * K + k0 + lk];
                sm.g.Ws[lk + 0][n] = v.x; sm.g.Ws[lk + 1][n] = v.y;
                sm.g.Ws[lk + 2][n] = v.z; sm.g.Ws[lk + 3][n] = v.w;
            }
            __syncthreads();
            #pragma unroll
            for (int kk = 0; kk < 32; kk++) {
                float a[8];
                *(float4*)&a[0] = *(const float4*)&sm.g.Xs[kk][mg * 8];
                *(float4*)&a[4] = *(const float4*)&sm.g.Xs[kk][mg * 8 + 4];
                float4 bv = *(const float4*)&sm.g.Ws[kk][col * 4];
                #pragma unroll
                for (int i2 = 0; i2 < 8; i2++) {
                    acc[i2].x += a[i2] * bv.x;
                    acc[i2].y += a[i2] * bv.y;
                    acc[i2].z += a[i2] * bv.z;
                    acc[i2].w += a[i2] * bv.w;
                }
            }
            __syncthreads();
        }
        float* dst = g_part + (size_t)ks * BB * N;
        #pragma unroll
        for (int i2 = 0; i2 < 8; i2++) {
            int m = mg * 8 + i2;
            *(float4*)&dst[(size_t)m * N + n0 + col * 4] = acc[i2];
        }
    }
}

// ---------------- LN (+ReLU), sums KS partials + bias ----------------
// mode 1: -> g_inter. mode 2: -> keys[i+1], vals[i+1], hidden, states[i+1].
__device__ void ln_phase(Smem& sm, const float* __restrict__ bias, const float* __restrict__ gam,
                         const float* __restrict__ bet, int N, int KS, int mode, int i,
                         float* __restrict__ out_states) {
    int b = blockIdx.x;
    if (b >= BB) return;
    int tid = threadIdx.x;
    float s = 0.f, ss = 0.f;
    for (int j = tid; j < N; j += 256) {
        float v = bias[j];
        for (int ks = 0; ks < KS; ks++) v += g_part[(size_t)ks * BB * N + b * N + j];
        sm.l.buf[j] = v;
        s += v; ss += v * v;
    }
    float mu = block_reduce(s, sm.l.red) / (float)N;
    float var = block_reduce(ss, sm.l.red) / (float)N - mu * mu;
    float rs = rsqrtf(var + 1e-5f);
    for (int j = tid; j < N; j += 256) {
        float y = fmaxf((sm.l.buf[j] - mu) * rs * gam[j] + bet[j], 0.f);
        if (mode == 1) {
            g_inter[b * 4096 + j] = y;
        } else {
            if (j < 1024)      g_keys[((size_t)(i + 1) * BB + b) * NHID + j] = y;
            else if (j < 2048) g_vals[((size_t)(i + 1) * BB + b) * NHID + (j - 1024)] = y;
            else {
                g_hidden[b * NHID + (j - 2048)] = y;
                out_states[((size_t)(i + 1) * BB + b) * NHID + (j - 2048)] = y;
            }
        }
    }
}

// ---------------- fused LN(q) + attention (one block per batch b) ----------------
__device__ void ln_attn_phase(Smem& sm, const float* __restrict__ bias, const float* __restrict__ gam,
                              const float* __restrict__ bet, int i) {
    int b = blockIdx.x;
    if (b >= BB) return;
    int tid = threadIdx.x;
    // LN over N=1024, KS=32 partials
    float s = 0.f, ss = 0.f;
    for (int j = tid; j < 1024; j += 256) {
        float v = bias[j];
        #pragma unroll
        for (int ks = 0; ks < 32; ks++) v += g_part[(size_t)ks * BB * 1024 + b * 1024 + j];
        sm.l.buf[j] = v;
        s += v; ss += v * v;
    }
    float mu = block_reduce(s, sm.l.red) / 1024.f;
    float var = block_reduce(ss, sm.l.red) / 1024.f - mu * mu;
    float rs = rsqrtf(var + 1e-5f);
    for (int j = tid; j < 1024; j += 256) {
        float y = fmaxf((sm.l.buf[j] - mu) * rs * gam[j] + bet[j], 0.f);
        sm.l.qs[j] = y;
        g_q[b * 1024 + j] = y;
    }
    __syncthreads();

    // attention: scores + softmax (warp w handles heads w, w+8)
    int len = i + 1;
    int warp = tid >> 5, lane = tid & 31;
    for (int hd = warp; hd < NH; hd += 8) {
        float sv[4];
        float mx = -1e30f;
        #pragma unroll
        for (int r = 0; r < 4; r++) {
            int c = lane + 32 * r;
            float d = -1e30f;
            if (c < len) {
                const float* kp = g_keys + ((size_t)c * BB + b) * NHID + hd * HDIM;
                float acc = 0.f;
                #pragma unroll
                for (int h = 0; h < HDIM; h += 4) {
                    float4 kv = *(const float4*)&kp[h];
                    acc += kv.x * sm.l.qs[hd * HDIM + h]     + kv.y * sm.l.qs[hd * HDIM + h + 1]
                         + kv.z * sm.l.qs[hd * HDIM + h + 2] + kv.w * sm.l.qs[hd * HDIM + h + 3];
                }
                d = acc * 0.125f;
            }
            sv[r] = d;
            mx = fmaxf(mx, d);
        }
        #pragma unroll
        for (int o = 16; o > 0; o >>= 1) mx = fmaxf(mx, __shfl_xor_sync(~0u, mx, o));
        float sum = 0.f;
        #pragma unroll
        for (int r = 0; r < 4; r++) {
            int c = lane + 32 * r;
            float e = (c < len) ? __expf(sv[r] - mx) : 0.f;
            sv[r] = e; sum += e;
        }
        #pragma unroll
        for (int o = 16; o > 0; o >>= 1) sum += __shfl_xor_sync(~0u, sum, o);
        float inv = 1.f / sum;
        #pragma unroll
        for (int r = 0; r < 4; r++) {
            int c = lane + 32 * r;
            if (c < len) sm.l.sc[hd][c] = sv[r] * inv;
        }
    }
    __syncthreads();

    // attn output: 16 heads x 64 dims
    for (int idx = tid; idx < 1024; idx += 256) {
        int hd = idx >> 6, h = idx & 63;
        float a = 0.f;
        const float* vp = g_vals + b * NHID + hd * HDIM + h;
        #pragma unroll 4
        for (int c = 0; c < len; c++) a += sm.l.sc[hd][c] * vp[(size_t)c * BB * NHID];
        g_attn[b * 1024 + idx] = a;
    }
}

// ---------------- the persistent sequence kernel ----------------
__global__ void __launch_bounds__(256, 1) k_seq(
    const float* __restrict__ q_w,   const float* __restrict__ q_b,
    const float* __restrict__ qn_g,  const float* __restrict__ qn_b,
    const float* __restrict__ int_w, const float* __restrict__ int_b,
    const float* __restrict__ intn_g,const float* __restrict__ intn_b,
    const float* __restrict__ fin_w, const float* __restrict__ fin_b,
    const float* __restrict__ fn_g,  const float* __restrict__ fn_b,
    float* __restrict__ out_states)
{
    __shared__ Smem sm;
    for (int i = 0; i < SS; i++) {
        // GEMM1: q_pre = [e|hidden] @ q_w^T   (N=1024, K=2048, KS=32 -> 128 tasks)
        {
            const float* segs[4] = { g_emb + (size_t)i * BB * NINP, g_hidden, g_hidden, g_hidden };
            gemm_phase(sm, segs, 10, 1024, q_w, 1024, 2048, 32);
        }
        gridbar();
        ln_attn_phase(sm, q_b, qn_g, qn_b, i);
        gridbar();
        // GEMM2: inter_pre = [e|q|attn|hidden] @ int_w^T  (N=4096, K=4096, KS=8 -> 128 tasks)
        {
            const float* segs[4] = { g_emb + (size_t)i * BB * NINP, g_q, g_attn, g_hidden };
            gemm_phase(sm, segs, 10, 1024, int_w, 4096, 4096, 8);
        }
        gridbar();
        ln_phase(sm, int_b, intn_g, intn_b, 4096, 8, 1, i, out_states);
        gridbar();
        // GEMM3: fin_pre = inter @ fin_w^T  (N=3072, K=4096, KS=8 -> 96 tasks)
        {
            const float* segs[4] = { g_inter, g_inter, g_inter, g_inter };
            gemm_phase(sm, segs, 12, 4096, fin_w, 3072, 4096, 8);
        }
        gridbar();
        ln_phase(sm, fin_b, fn_g, fn_b, 3072, 8, 2, i, out_states);
        gridbar();
    }
}

// ---------------- embedding gather ----------------
__global__ void k_embed(const int* __restrict__ obs, const float* __restrict__ enc_w) {
    int sb = blockIdx.x;
    int tok = obs[sb];
    const float4* src = (const float4*)(enc_w + (size_t)tok * NINP);
    float4* dst = (float4*)(g_emb + (size_t)sb * NINP);
    dst[threadIdx.x] = src[threadIdx.x];
}

// ---------------- init: hidden, caches, states_full[0], barrier state ----------------
__global__ void k_init(const float* __restrict__ hidden_init,
                       const float* __restrict__ kci,
                       const float* __restrict__ vci,
                       float* __restrict__ out_states) {
    if (blockIdx.x == 0 && threadIdx.x == 0) { g_cnt = 0; g_gen = 0; }
    int idx = blockIdx.x * 256 + threadIdx.x;  // 8192 float4s = B*NHID
    float4 h = ((const float4*)hidden_init)[idx];
    ((float4*)g_hidden)[idx] = h;
    ((float4*)out_states)[idx] = h;
    ((float4*)g_keys)[idx] = ((const float4*)kci)[idx];
    ((float4*)g_vals)[idx] = ((const float4*)vci)[idx];
}

// ---------------- decoder SGEMM: out[4096][32000] = X @ dec_w^T + dec_b ----------------
__global__ void __launch_bounds__(256, 2) k_dec(const float* __restrict__ X,
                                                const float* __restrict__ W,
                                                const float* __restrict__ bias,
                                                float* __restrict__ out) {
    __shared__ __align__(16) float As[8][132];
    __shared__ __align__(16) float Bs[8][132];
    const int m0 = blockIdx.x * 128;
    const int n0 = blockIdx.y * 128;
    const int tid = threadIdx.x;
    const int tx = tid & 15;
    const int ty = tid >> 4;

    float acc[8][8];
    #pragma unroll
    for (int i = 0; i < 8; i++)
        #pragma unroll
        for (int j = 0; j < 8; j++) acc[i][j] = 0.f;

    for (int k0 = 0; k0 < 1024; k0 += 8) {
        #pragma unroll
        for (int r = 0; r < 4; r++) {
            int e = tid + 256 * r;
            int mm = e >> 3;
            int kk = e & 7;
            As[kk][mm] = X[(size_t)(m0 + mm) * 1024 + k0 + kk];
            Bs[kk][mm] = W[(size_t)(n0 + mm) * 1024 + k0 + kk];
        }
        __syncthreads();
        #pragma unroll
        for (int kk = 0; kk < 8; kk++) {
            float a[8], bv[8];
            *(float4*)&a[0]  = *(const float4*)&As[kk][ty * 4];
            *(float4*)&a[4]  = *(const float4*)&As[kk][64 + ty * 4];
            *(float4*)&bv[0] = *(const float4*)&Bs[kk][tx * 4];
            *(float4*)&bv[4] = *(const float4*)&Bs[kk][64 + tx * 4];
            #pragma unroll
            for (int i = 0; i < 8; i++)
                #pragma unroll
                for (int j = 0; j < 8; j++) acc[i][j] += a[i] * bv[j];
        }
        __syncthreads();
    }
    #pragma unroll
    for (int i = 0; i < 8; i++) {
        int m = m0 + ((i < 4) ? (ty * 4 + i) : (64 + ty * 4 + (i - 4)));
        #pragma unroll
        for (int jh = 0; jh < 2; jh++) {
            int n = n0 + ((jh == 0) ? (tx * 4) : (64 + tx * 4));
            float4 v;
            v.x = acc[i][jh * 4 + 0] + bias[n + 0];
            v.y = acc[i][jh * 4 + 1] + bias[n + 1];
            v.z = acc[i][jh * 4 + 2] + bias[n + 2];
            v.w = acc[i][jh * 4 + 3] + bias[n + 3];
            *(float4*)&out[(size_t)m * VV + n] = v;
        }
    }
}

// ---------------- launch ----------------
extern "C" void kernel_launch(void* const* d_in, const int* in_sizes, int n_in,
                              void* d_out, int out_size) {
    const int*   obs         = (const int*)d_in[0];
    const float* hidden_init = (const float*)d_in[1];
    const float* kci         = (const float*)d_in[2];
    const float* vci         = (const float*)d_in[3];
    const float* enc_w       = (const float*)d_in[4];
    const float* q_w         = (const float*)d_in[5];
    const float* q_b         = (const float*)d_in[6];
    const float* qn_g        = (const float*)d_in[7];
    const float* qn_b        = (const float*)d_in[8];
    const float* int_w       = (const float*)d_in[9];
    const float* int_b       = (const float*)d_in[10];
    const float* intn_g      = (const float*)d_in[11];
    const float* intn_b      = (const float*)d_in[12];
    const float* fin_w       = (const float*)d_in[13];
    const float* fin_b       = (const float*)d_in[14];
    const float* fn_g        = (const float*)d_in[15];
    const float* fn_b        = (const float*)d_in[16];
    const float* dec_w       = (const float*)d_in[17];
    const float* dec_b       = (const float*)d_in[18];

    float* out        = (float*)d_out;
    float* out_states = out + (size_t)SS * BB * VV;

    k_embed<<<SS * BB, 256>>>(obs, enc_w);
    k_init<<<32, 256>>>(hidden_init, kci, vci, out_states);
    k_seq<<<NBLK, 256>>>(q_w, q_b, qn_g, qn_b, int_w, int_b, intn_g, intn_b,
                         fin_w, fin_b, fn_g, fn_b, out_states);
    const float* states = out_states + BB * NHID;
    k_dec<<<dim3(4096 / 128, VV / 128), 256>>>(states, dec_w, dec_b, out);
}

// round 4
// speedup vs baseline: 1.5465x; 1.5465x over previous
#include <cuda_runtime.h>
#include <cuda_bf16.h>
#include <math.h>

#define SS   128
#define BB   32
#define NINP 1024
#define NHID 1024
#define NH   16
#define HDIM 64
#define VV   32000
#define NBLK 148

// ---------------- scratch (device globals; no allocation) ----------------
__device__ float g_keys[(SS + 1) * BB * NHID];
__device__ float g_vals[(SS + 1) * BB * NHID];
__device__ float g_part[32 * BB * 1024];           // KS*B*N max = 1,048,576 floats
__device__ unsigned g_cnt;
__device__ unsigned g_gen;

// packed bf16 hi/lo (hi in low 16 bits, lo in high 16 bits)
__device__ unsigned g_qwp  [1024 * 2048];          // 8 MB
__device__ unsigned g_intwp[4096 * 4096];          // 67 MB
__device__ unsigned g_finwp[3072 * 4096];          // 50 MB
__device__ unsigned g_decwp[VV * 1024];            // 131 MB
__device__ unsigned g_embp [SS * BB * 1024];       // 16.8 MB
__device__ unsigned g_hidp [BB * 1024];
__device__ unsigned g_qp   [BB * 1024];
__device__ unsigned g_attnp[BB * 1024];
__device__ unsigned g_interp[BB * 4096];
__device__ unsigned g_spack[SS * BB * 1024];       // decoder input, packed

// ---------------- helpers ----------------
__device__ __forceinline__ unsigned packsplit(float x) {
    __nv_bfloat16 h = __float2bfloat16(x);
    __nv_bfloat16 l = __float2bfloat16(x - __bfloat162float(h));
    return (unsigned)__bfloat16_as_ushort(h) | ((unsigned)__bfloat16_as_ushort(l) << 16);
}
__device__ __forceinline__ unsigned prmt(unsigned a, unsigned b, unsigned s) {
    unsigned d; asm("prmt.b32 %0,%1,%2,%3;" : "=r"(d) : "r"(a), "r"(b), "r"(s)); return d;
}
__device__ __forceinline__ void mma16816(float* c, const unsigned* a, unsigned b0, unsigned b1) {
    asm volatile(
        "mma.sync.aligned.m16n8k16.row.col.f32.bf16.bf16.f32 "
        "{%0,%1,%2,%3}, {%4,%5,%6,%7}, {%8,%9}, {%0,%1,%2,%3};"
        : "+f"(c[0]), "+f"(c[1]), "+f"(c[2]), "+f"(c[3])
        : "r"(a[0]), "r"(a[1]), "r"(a[2]), "r"(a[3]), "r"(b0), "r"(b1));
}

// ---------------- grid barrier ----------------
__device__ __forceinline__ void gridbar() {
    __syncthreads();
    if (threadIdx.x == 0) {
        volatile unsigned* gen = &g_gen;
        unsigned g = *gen;
        __threadfence();
        if (atomicAdd(&g_cnt, 1u) == NBLK - 1) {
            g_cnt = 0;
            __threadfence();
            *gen = g + 1;
        } else {
            while (*gen == g) { }
        }
        __threadfence();
    }
    __syncthreads();
}

struct SmemL { float buf[4096]; float red[32]; float qs[1024]; float sc[16][132]; };

__device__ __forceinline__ float block_reduce(float v, float* red) {
    __syncthreads();
    int tid = threadIdx.x;
    #pragma unroll
    for (int o = 16; o > 0; o >>= 1) v += __shfl_xor_sync(~0u, v, o);
    if ((tid & 31) == 0) red[tid >> 5] = v;
    __syncthreads();
    if (tid < 8) {
        v = red[tid];
        #pragma unroll
        for (int o = 4; o > 0; o >>= 1) v += __shfl_xor_sync(0xff, v, o);
        if (tid == 0) red[0] = v;
    }
    __syncthreads();
    return red[0];
}

// ---------------- tensor-core GEMM phase (split-bf16, fp32 accurate) ----------------
// g_part[ks][32][N] = X[32 x K] @ W[N x K]^T restricted to k-chunk ks.
// Block tile: 32m x 256n, 8 warps each 32m x 32n. mma m16n8k16, 3 terms per product.
__device__ void gemm_mma(const unsigned* const* segs, int segshift, int xstride,
                         const unsigned* __restrict__ Wp, int N, int K, int KS) {
    const int ntasks = (N >> 8) * KS;
    const int Kc = K / KS;
    const int warp = threadIdx.x >> 5;
    const int lane = threadIdx.x & 31;
    const int g = lane >> 2;
    const int t = lane & 3;
    const unsigned kmask = (1u << segshift) - 1u;

    for (int task = blockIdx.x; task < ntasks; task += NBLK) {
        int nt = task / KS, ks = task - nt * KS;
        int n0 = (nt << 8) + (warp << 5);
        int k0b = ks * Kc;
        float acc[2][4][4];
        #pragma unroll
        for (int mt = 0; mt < 2; mt++)
            #pragma unroll
            for (int nti = 0; nti < 4; nti++)
                #pragma unroll
                for (int e = 0; e < 4; e++) acc[mt][nti][e] = 0.f;

        for (int k0 = k0b; k0 < k0b + Kc; k0 += 16) {
            const unsigned* xs = segs[k0 >> segshift];
            int ko = (int)(k0 & kmask) + t * 2;
            unsigned ahi[2][4], alo[2][4];
            #pragma unroll
            for (int mt = 0; mt < 2; mt++) {
                const unsigned* x0 = xs + (size_t)(mt * 16 + g) * xstride + ko;
                const unsigned* x8 = x0 + (size_t)8 * xstride;
                uint2 p0 = *(const uint2*)x0;
                uint2 p1 = *(const uint2*)x8;
                uint2 p2 = *(const uint2*)(x0 + 8);
                uint2 p3 = *(const uint2*)(x8 + 8);
                ahi[mt][0] = prmt(p0.x, p0.y, 0x5410); alo[mt][0] = prmt(p0.x, p0.y, 0x7632);
                ahi[mt][1] = prmt(p1.x, p1.y, 0x5410); alo[mt][1] = prmt(p1.x, p1.y, 0x7632);
                ahi[mt][2] = prmt(p2.x, p2.y, 0x5410); alo[mt][2] = prmt(p2.x, p2.y, 0x7632);
                ahi[mt][3] = prmt(p3.x, p3.y, 0x5410); alo[mt][3] = prmt(p3.x, p3.y, 0x7632);
            }
            #pragma unroll
            for (int nti = 0; nti < 4; nti++) {
                const unsigned* wr = Wp + (size_t)(n0 + nti * 8 + g) * K + k0 + t * 2;
                uint2 q0 = *(const uint2*)wr;
                uint2 q1 = *(const uint2*)(wr + 8);
                unsigned b0h = prmt(q0.x, q0.y, 0x5410), b0l = prmt(q0.x, q0.y, 0x7632);
                unsigned b1h = prmt(q1.x, q1.y, 0x5410), b1l = prmt(q1.x, q1.y, 0x7632);
                #pragma unroll
                for (int mt = 0; mt < 2; mt++) {
                    mma16816(acc[mt][nti], ahi[mt], b0h, b1h);
                    mma16816(acc[mt][nti], ahi[mt], b0l, b1l);
                    mma16816(acc[mt][nti], alo[mt], b0h, b1h);
                }
            }
        }
        float* dst = g_part + (size_t)ks * BB * N;
        #pragma unroll
        for (int mt = 0; mt < 2; mt++) {
            int m = mt * 16 + g;
            #pragma unroll
            for (int nti = 0; nti < 4; nti++) {
                int n = n0 + nti * 8 + t * 2;
                *(float2*)&dst[(size_t)m * N + n]       = make_float2(acc[mt][nti][0], acc[mt][nti][1]);
                *(float2*)&dst[(size_t)(m + 8) * N + n] = make_float2(acc[mt][nti][2], acc[mt][nti][3]);
            }
        }
    }
}

// ---------------- LN (+ReLU), sums KS partials + bias ----------------
__device__ void ln_phase(SmemL& sm, const float* __restrict__ bias, const float* __restrict__ gam,
                         const float* __restrict__ bet, int N, int KS, int mode, int i,
                         float* __restrict__ out_states) {
    int b = blockIdx.x;
    if (b >= BB) return;
    int tid = threadIdx.x;
    float s = 0.f, ss = 0.f;
    for (int j = tid; j < N; j += 256) {
        float v = bias[j];
        for (int ks = 0; ks < KS; ks++) v += g_part[(size_t)ks * BB * N + b * N + j];
        sm.buf[j] = v;
        s += v; ss += v * v;
    }
    float mu = block_reduce(s, sm.red) / (float)N;
    float var = block_reduce(ss, sm.red) / (float)N - mu * mu;
    float rs = rsqrtf(var + 1e-5f);
    for (int j = tid; j < N; j += 256) {
        float y = fmaxf((sm.buf[j] - mu) * rs * gam[j] + bet[j], 0.f);
        if (mode == 1) {
            g_interp[b * 4096 + j] = packsplit(y);
        } else {
            if (j < 1024)      g_keys[((size_t)(i + 1) * BB + b) * NHID + j] = y;
            else if (j < 2048) g_vals[((size_t)(i + 1) * BB + b) * NHID + (j - 1024)] = y;
            else {
                int jj = j - 2048;
                unsigned p = packsplit(y);
                g_hidp[b * 1024 + jj] = p;
                g_spack[((size_t)i * BB + b) * 1024 + jj] = p;
                out_states[((size_t)(i + 1) * BB + b) * NHID + jj] = y;
            }
        }
    }
}

// ---------------- fused LN(q) + attention ----------------
__device__ void ln_attn_phase(SmemL& sm, const float* __restrict__ bias, const float* __restrict__ gam,
                              const float* __restrict__ bet, int i) {
    int b = blockIdx.x;
    if (b >= BB) return;
    int tid = threadIdx.x;
    float s = 0.f, ss = 0.f;
    for (int j = tid; j < 1024; j += 256) {
        float v = bias[j];
        #pragma unroll
        for (int ks = 0; ks < 32; ks++) v += g_part[(size_t)ks * BB * 1024 + b * 1024 + j];
        sm.buf[j] = v;
        s += v; ss += v * v;
    }
    float mu = block_reduce(s, sm.red) / 1024.f;
    float var = block_reduce(ss, sm.red) / 1024.f - mu * mu;
    float rs = rsqrtf(var + 1e-5f);
    for (int j = tid; j < 1024; j += 256) {
        float y = fmaxf((sm.buf[j] - mu) * rs * gam[j] + bet[j], 0.f);
        sm.qs[j] = y;
        g_qp[b * 1024 + j] = packsplit(y);
    }
    __syncthreads();

    int len = i + 1;
    int warp = tid >> 5, lane = tid & 31;
    for (int hd = warp; hd < NH; hd += 8) {
        float sv[4];
        float mx = -1e30f;
        #pragma unroll
        for (int r = 0; r < 4; r++) {
            int c = lane + 32 * r;
            float d = -1e30f;
            if (c < len) {
                const float* kp = g_keys + ((size_t)c * BB + b) * NHID + hd * HDIM;
                float a2 = 0.f;
                #pragma unroll
                for (int h = 0; h < HDIM; h += 4) {
                    float4 kv = *(const float4*)&kp[h];
                    a2 += kv.x * sm.qs[hd * HDIM + h]     + kv.y * sm.qs[hd * HDIM + h + 1]
                        + kv.z * sm.qs[hd * HDIM + h + 2] + kv.w * sm.qs[hd * HDIM + h + 3];
                }
                d = a2 * 0.125f;
            }
            sv[r] = d;
            mx = fmaxf(mx, d);
        }
        #pragma unroll
        for (int o = 16; o > 0; o >>= 1) mx = fmaxf(mx, __shfl_xor_sync(~0u, mx, o));
        float sum = 0.f;
        #pragma unroll
        for (int r = 0; r < 4; r++) {
            int c = lane + 32 * r;
            float e = (c < len) ? __expf(sv[r] - mx) : 0.f;
            sv[r] = e; sum += e;
        }
        #pragma unroll
        for (int o = 16; o > 0; o >>= 1) sum += __shfl_xor_sync(~0u, sum, o);
        float inv = 1.f / sum;
        #pragma unroll
        for (int r = 0; r < 4; r++) {
            int c = lane + 32 * r;
            if (c < len) sm.sc[hd][c] = sv[r] * inv;
        }
    }
    __syncthreads();

    for (int idx = tid; idx < 1024; idx += 256) {
        int hd = idx >> 6, h = idx & 63;
        float a = 0.f;
        const float* vp = g_vals + b * NHID + hd * HDIM + h;
        #pragma unroll 4
        for (int c = 0; c < len; c++) a += sm.sc[hd][c] * vp[(size_t)c * BB * NHID];
        g_attnp[b * 1024 + idx] = packsplit(a);
    }
}

// ---------------- persistent sequence kernel ----------------
__global__ void __launch_bounds__(256, 1) k_seq(
    const float* __restrict__ q_b,   const float* __restrict__ qn_g,  const float* __restrict__ qn_b,
    const float* __restrict__ int_b, const float* __restrict__ intn_g,const float* __restrict__ intn_b,
    const float* __restrict__ fin_b, const float* __restrict__ fn_g,  const float* __restrict__ fn_b,
    float* __restrict__ out_states)
{
    __shared__ SmemL sm;
    for (int i = 0; i < SS; i++) {
        {   // GEMM1: [e|hidden] @ q_w^T  (N=1024, K=2048, KS=32 -> 128 tasks)
            const unsigned* segs[4] = { g_embp + (size_t)i * BB * 1024, g_hidp, g_hidp, g_hidp };
            gemm_mma(segs, 10, 1024, g_qwp, 1024, 2048, 32);
        }
        gridbar();
        ln_attn_phase(sm, q_b, qn_g, qn_b, i);
        gridbar();
        {   // GEMM2: [e|q|attn|hidden] @ int_w^T  (N=4096, K=4096, KS=8 -> 128 tasks)
            const unsigned* segs[4] = { g_embp + (size_t)i * BB * 1024, g_qp, g_attnp, g_hidp };
            gemm_mma(segs, 10, 1024, g_intwp, 4096, 4096, 8);
        }
        gridbar();
        ln_phase(sm, int_b, intn_g, intn_b, 4096, 8, 1, i, out_states);
        gridbar();
        {   // GEMM3: inter @ fin_w^T  (N=3072, K=4096, KS=8 -> 96 tasks)
            const unsigned* segs[4] = { g_interp, g_interp, g_interp, g_interp };
            gemm_mma(segs, 12, 4096, g_finwp, 3072, 4096, 8);
        }
        gridbar();
        ln_phase(sm, fin_b, fn_g, fn_b, 3072, 8, 2, i, out_states);
        gridbar();
    }
}

// ---------------- weight split/pack ----------------
__global__ void k_convert(const float* __restrict__ w, unsigned* __restrict__ wp, int n) {
    for (int i = blockIdx.x * 256 + threadIdx.x; i < n; i += gridDim.x * 256)
        wp[i] = packsplit(w[i]);
}

// ---------------- embedding gather (packed) ----------------
__global__ void k_embed(const int* __restrict__ obs, const float* __restrict__ enc_w) {
    int sb = blockIdx.x;
    int tok = obs[sb];
    const float4* src = (const float4*)(enc_w + (size_t)tok * NINP);
    float4 v = src[threadIdx.x];
    uint4 p = make_uint4(packsplit(v.x), packsplit(v.y), packsplit(v.z), packsplit(v.w));
    ((uint4*)(g_embp + (size_t)sb * NINP))[threadIdx.x] = p;
}

// ---------------- init ----------------
__global__ void k_init(const float* __restrict__ hidden_init,
                       const float* __restrict__ kci,
                       const float* __restrict__ vci,
                       float* __restrict__ out_states) {
    if (blockIdx.x == 0 && threadIdx.x == 0) { g_cnt = 0; g_gen = 0; }
    int idx = blockIdx.x * 256 + threadIdx.x;        // 8192 float4s
    float4 h = ((const float4*)hidden_init)[idx];
    ((float4*)out_states)[idx] = h;
    ((float4*)g_keys)[idx] = ((const float4*)kci)[idx];
    ((float4*)g_vals)[idx] = ((const float4*)vci)[idx];
    uint4 p = make_uint4(packsplit(h.x), packsplit(h.y), packsplit(h.z), packsplit(h.w));
    ((uint4*)g_hidp)[idx] = p;
}

// ---------------- decoder (tensor-core): out[4096][32000] = states @ dec_w^T + dec_b
__global__ void __launch_bounds__(256, 2) k_dec(const float* __restrict__ bias,
                                                float* __restrict__ out) {
    const int m0 = blockIdx.x * 128;
    const int n0 = blockIdx.y * 128;
    const int warp = threadIdx.x >> 5;
    const int lane = threadIdx.x & 31;
    const int g = lane >> 2;
    const int t = lane & 3;
    const int mb = m0 + (warp & 3) * 32;
    const int nb = n0 + (warp >> 2) * 64;

    float acc[2][8][4];
    #pragma unroll
    for (int mt = 0; mt < 2; mt++)
        #pragma unroll
        for (int nti = 0; nti < 8; nti++)
            #pragma unroll
            for (int e = 0; e < 4; e++) acc[mt][nti][e] = 0.f;

    for (int k0 = 0; k0 < 1024; k0 += 16) {
        unsigned ahi[2][4], alo[2][4];
        #pragma unroll
        for (int mt = 0; mt < 2; mt++) {
            const unsigned* x0 = g_spack + (size_t)(mb + mt * 16 + g) * 1024 + k0 + t * 2;
            const unsigned* x8 = x0 + 8 * 1024;
            uint2 p0 = *(const uint2*)x0;
            uint2 p1 = *(const uint2*)x8;
            uint2 p2 = *(const uint2*)(x0 + 8);
            uint2 p3 = *(const uint2*)(x8 + 8);
            ahi[mt][0] = prmt(p0.x, p0.y, 0x5410); alo[mt][0] = prmt(p0.x, p0.y, 0x7632);
            ahi[mt][1] = prmt(p1.x, p1.y, 0x5410); alo[mt][1] = prmt(p1.x, p1.y, 0x7632);
            ahi[mt][2] = prmt(p2.x, p2.y, 0x5410); alo[mt][2] = prmt(p2.x, p2.y, 0x7632);
            ahi[mt][3] = prmt(p3.x, p3.y, 0x5410); alo[mt][3] = prmt(p3.x, p3.y, 0x7632);
        }
        #pragma unroll
        for (int nti = 0; nti < 8; nti++) {
            const unsigned* wr = g_decwp + (size_t)(nb + nti * 8 + g) * 1024 + k0 + t * 2;
            uint2 q0 = *(const uint2*)wr;
            uint2 q1 = *(const uint2*)(wr + 8);
            unsigned b0h = prmt(q0.x, q0.y, 0x5410), b0l = prmt(q0.x, q0.y, 0x7632);
            unsigned b1h = prmt(q1.x, q1.y, 0x5410), b1l = prmt(q1.x, q1.y, 0x7632);
            #pragma unroll
            for (int mt = 0; mt < 2; mt++) {
                mma16816(acc[mt][nti], ahi[mt], b0h, b1h);
                mma16816(acc[mt][nti], ahi[mt], b0l, b1l);
                mma16816(acc[mt][nti], alo[mt], b0h, b1h);
            }
        }
    }
    #pragma unroll
    for (int mt = 0; mt < 2; mt++) {
        int m = mb + mt * 16 + g;
        #pragma unroll
        for (int nti = 0; nti < 8; nti++) {
            int n = nb + nti * 8 + t * 2;
            float bx = bias[n], by = bias[n + 1];
            *(float2*)&out[(size_t)m * VV + n]       = make_float2(acc[mt][nti][0] + bx, acc[mt][nti][1] + by);
            *(float2*)&out[(size_t)(m + 8) * VV + n] = make_float2(acc[mt][nti][2] + bx, acc[mt][nti][3] + by);
        }
    }
}

// ---------------- launch ----------------
extern "C" void kernel_launch(void* const* d_in, const int* in_sizes, int n_in,
                              void* d_out, int out_size) {
    const int*   obs         = (const int*)d_in[0];
    const float* hidden_init = (const float*)d_in[1];
    const float* kci         = (const float*)d_in[2];
    const float* vci         = (const float*)d_in[3];
    const float* enc_w       = (const float*)d_in[4];
    const float* q_w         = (const float*)d_in[5];
    const float* q_b         = (const float*)d_in[6];
    const float* qn_g        = (const float*)d_in[7];
    const float* qn_b        = (const float*)d_in[8];
    const float* int_w       = (const float*)d_in[9];
    const float* int_b       = (const float*)d_in[10];
    const float* intn_g      = (const float*)d_in[11];
    const float* intn_b      = (const float*)d_in[12];
    const float* fin_w       = (const float*)d_in[13];
    const float* fin_b       = (const float*)d_in[14];
    const float* fn_g        = (const float*)d_in[15];
    const float* fn_b        = (const float*)d_in[16];
    const float* dec_w       = (const float*)d_in[17];
    const float* dec_b       = (const float*)d_in[18];

    float* out        = (float*)d_out;
    float* out_states = out + (size_t)SS * BB * VV;

    unsigned* qwp;  cudaGetSymbolAddress((void**)&qwp,  g_qwp);
    unsigned* iwp;  cudaGetSymbolAddress((void**)&iwp,  g_intwp);
    unsigned* fwp;  cudaGetSymbolAddress((void**)&fwp,  g_finwp);
    unsigned* dwp;  cudaGetSymbolAddress((void**)&dwp,  g_decwp);

    k_convert<<<4096, 256>>>(q_w,   qwp, 1024 * 2048);
    k_convert<<<4096, 256>>>(int_w, iwp, 4096 * 4096);
    k_convert<<<4096, 256>>>(fin_w, fwp, 3072 * 4096);
    k_convert<<<4096, 256>>>(dec_w, dwp, VV * 1024);

    k_embed<<<SS * BB, 256>>>(obs, enc_w);
    k_init<<<32, 256>>>(hidden_init, kci, vci, out_states);
    k_seq<<<NBLK, 256>>>(q_b, qn_g, qn_b, int_b, intn_g, intn_b,
                         fin_b, fn_g, fn_b, out_states);
    k_dec<<<dim3(4096 / 128, VV / 128), 256>>>(dec_b, out);
}

// round 5
// speedup vs baseline: 2.1404x; 1.3840x over previous
#include <cuda_runtime.h>
#include <cuda_bf16.h>
#include <math.h>

#define SS   128
#define BB   32
#define NINP 1024
#define NHID 1024
#define NH   16
#define HDIM 64
#define VV   32000
#define NBLK 148

// ---------------- scratch (device globals; no allocation) ----------------
__device__ float g_keys[(SS + 1) * BB * NHID];
__device__ float g_vals[(SS + 1) * BB * NHID];
__device__ float g_part[32 * BB * 1024];                       // 1M floats (4 MB)
__device__ unsigned g_cnt;
__device__ unsigned g_gen;

// fragment-ordered packed bf16 hi/lo weights
__device__ __align__(16) unsigned g_qwp  [1024 * 2048];
__device__ __align__(16) unsigned g_intwp[4096 * 4096];
__device__ __align__(16) unsigned g_finwp[3072 * 4096];
__device__ __align__(16) unsigned g_decwp[VV * 1024];
// plain row-major packed activations
__device__ __align__(16) unsigned g_embp [SS * BB * 1024];
__device__ __align__(16) unsigned g_hidp [BB * 1024];
__device__ __align__(16) unsigned g_qp   [BB * 1024];
__device__ __align__(16) unsigned g_attnp[BB * 1024];
__device__ __align__(16) unsigned g_interp[BB * 4096];
__device__ __align__(16) unsigned g_spack[SS * BB * 1024];

// ---------------- helpers ----------------
__device__ __forceinline__ unsigned packsplit(float x) {
    __nv_bfloat16 h = __float2bfloat16(x);
    __nv_bfloat16 l = __float2bfloat16(x - __bfloat162float(h));
    return (unsigned)__bfloat16_as_ushort(h) | ((unsigned)__bfloat16_as_ushort(l) << 16);
}
__device__ __forceinline__ unsigned prmt(unsigned a, unsigned b, unsigned s) {
    unsigned d; asm("prmt.b32 %0,%1,%2,%3;" : "=r"(d) : "r"(a), "r"(b), "r"(s)); return d;
}
__device__ __forceinline__ void mma16816(float* c, const unsigned* a, unsigned b0, unsigned b1) {
    asm volatile(
        "mma.sync.aligned.m16n8k16.row.col.f32.bf16.bf16.f32 "
        "{%0,%1,%2,%3}, {%4,%5,%6,%7}, {%8,%9}, {%0,%1,%2,%3};"
        : "+f"(c[0]), "+f"(c[1]), "+f"(c[2]), "+f"(c[3])
        : "r"(a[0]), "r"(a[1]), "r"(a[2]), "r"(a[3]), "r"(b0), "r"(b1));
}

// ---------------- grid barrier ----------------
__device__ __forceinline__ void gridbar() {
    __syncthreads();
    if (threadIdx.x == 0) {
        volatile unsigned* gen = &g_gen;
        unsigned g = *gen;
        __threadfence();
        if (atomicAdd(&g_cnt, 1u) == NBLK - 1) {
            g_cnt = 0;
            __threadfence();
            *gen = g + 1;
        } else {
            while (*gen == g) { __nanosleep(64); }
        }
        __threadfence();
    }
    __syncthreads();
}

struct SmemL { float buf[4096]; float red[32]; float qs[1024]; float sc[16][132]; };
union SmemU {
    __align__(16) unsigned af[4096];   // 2 buffers x (2 planes x 1024 words) = 16 KB
    SmemL l;
};

__device__ __forceinline__ float block_reduce(float v, float* red) {
    __syncthreads();
    int tid = threadIdx.x;
    #pragma unroll
    for (int o = 16; o > 0; o >>= 1) v += __shfl_xor_sync(~0u, v, o);
    if ((tid & 31) == 0) red[tid >> 5] = v;
    __syncthreads();
    if (tid < 16) {
        v = red[tid];
        #pragma unroll
        for (int o = 8; o > 0; o >>= 1) v += __shfl_xor_sync(0xffff, v, o);
        if (tid == 0) red[0] = v;
    }
    __syncthreads();
    return red[0];
}

// ---------------- GEMM phase (split-bf16 tensor core, fragment layouts) ----------------
__device__ __forceinline__ const uint4* stage_addr(const unsigned* const* segs, int segshift,
                                                   unsigned kmask, int xstride, int k0,
                                                   int sm_m, int sm_j) {
    const unsigned* seg = segs[k0 >> segshift];
    return (const uint4*)(seg + (size_t)sm_m * xstride + (k0 & kmask) + sm_j * 4);
}

// g_part[ks][32][N] = X[32 x K] @ W[N x K]^T on k-chunk ks. Block tile 32m x 256n,
// 16 warps each 32m x 16n. A double-buffered in smem (pre-split hi/lo fragments).
__device__ void gemm_mma(unsigned* af, const unsigned* const* segs, int segshift, int xstride,
                         const unsigned* __restrict__ Wf, int N, int K, int KS) {
    const int ntasks = (N >> 8) * KS;
    const int Kc = K / KS;
    const int nc = Kc >> 6;                 // 64-k chunks per task
    const unsigned kmask = (1u << segshift) - 1u;
    const int tid = threadIdx.x;
    const int warp = tid >> 5, lane = tid & 31;
    const int t = lane & 3, gq = lane >> 2;
    const int K16tot = K >> 4;

    // staging role: thread -> (m = tid>>4, k4-group j = tid&15)
    const int sm_m = tid >> 4, sm_j = tid & 15;
    const int s_row = sm_m & 15, s_g = s_row & 7, s_rh = s_row >> 3, s_mt = sm_m >> 4;
    const int s_k16 = sm_j >> 2, s_kb = (sm_j & 3) << 2;
    const int s_t0 = (s_kb >> 1) & 3;
    const int s_w = s_rh + ((s_kb >> 3) << 1);
    const int s_base = ((s_k16 * 2 + s_mt) * 32 + s_g * 4 + s_t0) * 4 + s_w;

    int task = blockIdx.x;
    if (task >= ntasks) return;
    int cc = 0;
    uint4 v = *stage_addr(segs, segshift, kmask, xstride, (task % KS) * Kc, sm_m, sm_j);

    for (; task < ntasks; task += NBLK) {
        const int nt = task / KS, ks = task - nt * KS;
        const int n0w = (nt << 8) + (warp << 4);
        const int k0b = ks * Kc;
        float acc[2][2][4];
        #pragma unroll
        for (int mt = 0; mt < 2; mt++)
            #pragma unroll
            for (int nti = 0; nti < 2; nti++)
                #pragma unroll
                for (int e = 0; e < 4; e++) acc[mt][nti][e] = 0.f;

        for (int c = 0; c < nc; c++) {
            unsigned* buf = af + (cc & 1) * 2048; cc++;
            // stage current chunk (pre-split hi/lo into fragment order)
            buf[s_base]            = prmt(v.x, v.y, 0x5410);
            buf[s_base + 4]        = prmt(v.z, v.w, 0x5410);
            buf[1024 + s_base]     = prmt(v.x, v.y, 0x7632);
            buf[1024 + s_base + 4] = prmt(v.z, v.w, 0x7632);
            __syncthreads();
            // prefetch next chunk
            if (c + 1 < nc) {
                v = *stage_addr(segs, segshift, kmask, xstride, k0b + (c + 1) * 64, sm_m, sm_j);
            } else if (task + NBLK < ntasks) {
                int t2 = task + NBLK;
                v = *stage_addr(segs, segshift, kmask, xstride, (t2 % KS) * Kc, sm_m, sm_j);
            }
            // consume 4 k16 steps
            const int k16g0 = (k0b + c * 64) >> 4;
            #pragma unroll
            for (int kk = 0; kk < 4; kk++) {
                unsigned ah[2][4], al[2][4];
                #pragma unroll
                for (int mt = 0; mt < 2; mt++) {
                    *(uint4*)ah[mt] = *(const uint4*)&buf[((kk * 2 + mt) * 32 + lane) * 4];
                    *(uint4*)al[mt] = *(const uint4*)&buf[1024 + ((kk * 2 + mt) * 32 + lane) * 4];
                }
                #pragma unroll
                for (int nti = 0; nti < 2; nti++) {
                    int n8 = (n0w >> 3) + nti;
                    const uint4 q = *(const uint4*)(Wf + (((size_t)n8 * K16tot + k16g0 + kk) * 32 + lane) * 4);
                    unsigned b0h = prmt(q.x, q.y, 0x5410), b0l = prmt(q.x, q.y, 0x7632);
                    unsigned b1h = prmt(q.z, q.w, 0x5410), b1l = prmt(q.z, q.w, 0x7632);
                    #pragma unroll
                    for (int mt = 0; mt < 2; mt++) {
                        mma16816(acc[mt][nti], ah[mt], b0h, b1h);
                        mma16816(acc[mt][nti], ah[mt], b0l, b1l);
                        mma16816(acc[mt][nti], al[mt], b0h, b1h);
                    }
                }
            }
        }
        float* dst = g_part + (size_t)ks * BB * N;
        #pragma unroll
        for (int mt = 0; mt < 2; mt++) {
            int m = mt * 16 + gq;
            #pragma unroll
            for (int nti = 0; nti < 2; nti++) {
                int n = n0w + nti * 8 + t * 2;
                *(float2*)&dst[(size_t)m * N + n]       = make_float2(acc[mt][nti][0], acc[mt][nti][1]);
                *(float2*)&dst[(size_t)(m + 8) * N + n] = make_float2(acc[mt][nti][2], acc[mt][nti][3]);
            }
        }
    }
}

// ---------------- LN (+ReLU), sums KS partials + bias ----------------
__device__ void ln_phase(SmemL& sm, const float* __restrict__ bias, const float* __restrict__ gam,
                         const float* __restrict__ bet, int N, int KS, int mode, int i,
                         float* __restrict__ out_states) {
    int b = blockIdx.x;
    if (b >= BB) return;
    int tid = threadIdx.x;
    float s = 0.f, ss = 0.f;
    for (int j = tid; j < N; j += 512) {
        float v = bias[j];
        for (int ks = 0; ks < KS; ks++) v += g_part[(size_t)ks * BB * N + b * N + j];
        sm.buf[j] = v;
        s += v; ss += v * v;
    }
    float mu = block_reduce(s, sm.red) / (float)N;
    float var = block_reduce(ss, sm.red) / (float)N - mu * mu;
    float rs = rsqrtf(var + 1e-5f);
    for (int j = tid; j < N; j += 512) {
        float y = fmaxf((sm.buf[j] - mu) * rs * gam[j] + bet[j], 0.f);
        if (mode == 1) {
            g_interp[b * 4096 + j] = packsplit(y);
        } else {
            if (j < 1024)      g_keys[((size_t)(i + 1) * BB + b) * NHID + j] = y;
            else if (j < 2048) g_vals[((size_t)(i + 1) * BB + b) * NHID + (j - 1024)] = y;
            else {
                int jj = j - 2048;
                unsigned p = packsplit(y);
                g_hidp[b * 1024 + jj] = p;
                g_spack[((size_t)i * BB + b) * 1024 + jj] = p;
                out_states[((size_t)(i + 1) * BB + b) * NHID + jj] = y;
            }
        }
    }
}

// ---------------- fused LN(q) + attention ----------------
__device__ void ln_attn_phase(SmemL& sm, const float* __restrict__ bias, const float* __restrict__ gam,
                              const float* __restrict__ bet, int i) {
    int b = blockIdx.x;
    if (b >= BB) return;
    int tid = threadIdx.x;
    float s = 0.f, ss = 0.f;
    for (int j = tid; j < 1024; j += 512) {
        float v = bias[j];
        #pragma unroll
        for (int ks = 0; ks < 32; ks++) v += g_part[(size_t)ks * BB * 1024 + b * 1024 + j];
        sm.buf[j] = v;
        s += v; ss += v * v;
    }
    float mu = block_reduce(s, sm.red) / 1024.f;
    float var = block_reduce(ss, sm.red) / 1024.f - mu * mu;
    float rs = rsqrtf(var + 1e-5f);
    for (int j = tid; j < 1024; j += 512) {
        float y = fmaxf((sm.buf[j] - mu) * rs * gam[j] + bet[j], 0.f);
        sm.qs[j] = y;
        g_qp[b * 1024 + j] = packsplit(y);
    }
    __syncthreads();

    int len = i + 1;
    int hd = tid >> 5, lane = tid & 31;   // one head per warp (16 warps)
    {
        float sv[4];
        float mx = -1e30f;
        #pragma unroll
        for (int r = 0; r < 4; r++) {
            int c = lane + 32 * r;
            float d = -1e30f;
            if (c < len) {
                const float* kp = g_keys + ((size_t)c * BB + b) * NHID + hd * HDIM;
                float a2 = 0.f;
                #pragma unroll
                for (int h = 0; h < HDIM; h += 4) {
                    float4 kv = *(const float4*)&kp[h];
                    a2 += kv.x * sm.qs[hd * HDIM + h]     + kv.y * sm.qs[hd * HDIM + h + 1]
                        + kv.z * sm.qs[hd * HDIM + h + 2] + kv.w * sm.qs[hd * HDIM + h + 3];
                }
                d = a2 * 0.125f;
            }
            sv[r] = d;
            mx = fmaxf(mx, d);
        }
        #pragma unroll
        for (int o = 16; o > 0; o >>= 1) mx = fmaxf(mx, __shfl_xor_sync(~0u, mx, o));
        float sum = 0.f;
        #pragma unroll
        for (int r = 0; r < 4; r++) {
            int c = lane + 32 * r;
            float e = (c < len) ? __expf(sv[r] - mx) : 0.f;
            sv[r] = e; sum += e;
        }
        #pragma unroll
        for (int o = 16; o > 0; o >>= 1) sum += __shfl_xor_sync(~0u, sum, o);
        float inv = 1.f / sum;
        #pragma unroll
        for (int r = 0; r < 4; r++) {
            int c = lane + 32 * r;
            if (c < len) sm.sc[hd][c] = sv[r] * inv;
        }
    }
    __syncthreads();

    for (int idx = tid; idx < 1024; idx += 512) {
        int h2 = idx >> 6, h = idx & 63;
        float a = 0.f;
        const float* vp = g_vals + b * NHID + h2 * HDIM + h;
        #pragma unroll 4
        for (int c = 0; c < len; c++) a += sm.sc[h2][c] * vp[(size_t)c * BB * NHID];
        g_attnp[b * 1024 + idx] = packsplit(a);
    }
}

// ---------------- persistent sequence kernel ----------------
__global__ void __launch_bounds__(512, 1) k_seq(
    const float* __restrict__ q_b,   const float* __restrict__ qn_g,  const float* __restrict__ qn_b,
    const float* __restrict__ int_b, const float* __restrict__ intn_g,const float* __restrict__ intn_b,
    const float* __restrict__ fin_b, const float* __restrict__ fn_g,  const float* __restrict__ fn_b,
    float* __restrict__ out_states)
{
    __shared__ SmemU sm;
    for (int i = 0; i < SS; i++) {
        {   // GEMM1: [e|hidden] @ q_w^T  (N=1024, K=2048, KS=32 -> 128 tasks)
            const unsigned* segs[4] = { g_embp + (size_t)i * BB * 1024, g_hidp, g_hidp, g_hidp };
            gemm_mma(sm.af, segs, 10, 1024, g_qwp, 1024, 2048, 32);
        }
        gridbar();
        ln_attn_phase(sm.l, q_b, qn_g, qn_b, i);
        gridbar();
        {   // GEMM2: [e|q|attn|hidden] @ int_w^T  (N=4096, K=4096, KS=8 -> 128 tasks)
            const unsigned* segs[4] = { g_embp + (size_t)i * BB * 1024, g_qp, g_attnp, g_hidp };
            gemm_mma(sm.af, segs, 10, 1024, g_intwp, 4096, 4096, 8);
        }
        gridbar();
        ln_phase(sm.l, int_b, intn_g, intn_b, 4096, 8, 1, i, out_states);
        gridbar();
        {   // GEMM3: inter @ fin_w^T  (N=3072, K=4096, KS=8 -> 96 tasks)
            const unsigned* segs[4] = { g_interp, g_interp, g_interp, g_interp };
            gemm_mma(sm.af, segs, 12, 4096, g_finwp, 3072, 4096, 8);
        }
        gridbar();
        ln_phase(sm.l, fin_b, fn_g, fn_b, 3072, 8, 2, i, out_states);
        gridbar();
    }
}

// ---------------- weight convert: split + fragment reorder ----------------
__global__ void k_convert_frag(const float* __restrict__ w, unsigned* __restrict__ wf,
                               int total, int kshift) {
    const int K = 1 << kshift;
    for (int i = blockIdx.x * 256 + threadIdx.x; i < total; i += gridDim.x * 256) {
        int k = i & (K - 1);
        int n = i >> kshift;
        unsigned p = packsplit(w[i]);
        int n8 = n >> 3, g = n & 7;
        int k16 = k >> 4, kr = k & 15;
        int t = (kr >> 1) & 3, wd = (kr & 1) + ((kr >> 3) << 1);
        wf[(((size_t)n8 * (K >> 4) + k16) * 32 + g * 4 + t) * 4 + wd] = p;
    }
}

// ---------------- embedding gather (packed) ----------------
__global__ void k_embed(const int* __restrict__ obs, const float* __restrict__ enc_w) {
    int sb = blockIdx.x;
    int tok = obs[sb];
    const float4* src = (const float4*)(enc_w + (size_t)tok * NINP);
    float4 v = src[threadIdx.x];
    uint4 p = make_uint4(packsplit(v.x), packsplit(v.y), packsplit(v.z), packsplit(v.w));
    ((uint4*)(g_embp + (size_t)sb * NINP))[threadIdx.x] = p;
}

// ---------------- init ----------------
__global__ void k_init(const float* __restrict__ hidden_init,
                       const float* __restrict__ kci,
                       const float* __restrict__ vci,
                       float* __restrict__ out_states) {
    if (blockIdx.x == 0 && threadIdx.x == 0) { g_cnt = 0; g_gen = 0; }
    int idx = blockIdx.x * 256 + threadIdx.x;        // 8192 float4s
    float4 h = ((const float4*)hidden_init)[idx];
    ((float4*)out_states)[idx] = h;
    ((float4*)g_keys)[idx] = ((const float4*)kci)[idx];
    ((float4*)g_vals)[idx] = ((const float4*)vci)[idx];
    uint4 p = make_uint4(packsplit(h.x), packsplit(h.y), packsplit(h.z), packsplit(h.w));
    ((uint4*)g_hidp)[idx] = p;
}

// ---------------- decoder: out[4096][32000] = states @ dec_w^T + dec_b ----------------
// Block 128m x 256n, 512 threads; warp = 32m x 64n (8 n8-tiles). Fragment-ordered W.
__global__ void __launch_bounds__(512, 1) k_dec(const float* __restrict__ bias,
                                                float* __restrict__ out) {
    const int m0 = blockIdx.x * 128;
    const int n0 = blockIdx.y * 256;
    const int warp = threadIdx.x >> 5, lane = threadIdx.x & 31;
    const int g = lane >> 2, t = lane & 3;
    const int mb = m0 + (warp & 3) * 32;
    const int nb = n0 + (warp >> 2) * 64;
    const int n8b = nb >> 3;

    float acc[2][8][4];
    #pragma unroll
    for (int mt = 0; mt < 2; mt++)
        #pragma unroll
        for (int ni = 0; ni < 8; ni++)
            #pragma unroll
            for (int e = 0; e < 4; e++) acc[mt][ni][e] = 0.f;

    for (int k0 = 0; k0 < 1024; k0 += 16) {
        unsigned ahi[2][4], alo[2][4];
        #pragma unroll
        for (int mt = 0; mt < 2; mt++) {
            const unsigned* x0 = g_spack + (size_t)(mb + mt * 16 + g) * 1024 + k0 + t * 2;
            const unsigned* x8 = x0 + 8 * 1024;
            uint2 p0 = *(const uint2*)x0;
            uint2 p1 = *(const uint2*)x8;
            uint2 p2 = *(const uint2*)(x0 + 8);
            uint2 p3 = *(const uint2*)(x8 + 8);
            ahi[mt][0] = prmt(p0.x, p0.y, 0x5410); alo[mt][0] = prmt(p0.x, p0.y, 0x7632);
            ahi[mt][1] = prmt(p1.x, p1.y, 0x5410); alo[mt][1] = prmt(p1.x, p1.y, 0x7632);
            ahi[mt][2] = prmt(p2.x, p2.y, 0x5410); alo[mt][2] = prmt(p2.x, p2.y, 0x7632);
            ahi[mt][3] = prmt(p3.x, p3.y, 0x5410); alo[mt][3] = prmt(p3.x, p3.y, 0x7632);
        }
        #pragma unroll
        for (int ni = 0; ni < 8; ni++) {
            const uint4 q = *(const uint4*)(g_decwp + (((size_t)(n8b + ni) * 64 + (k0 >> 4)) * 32 + lane) * 4);
            unsigned b0h = prmt(q.x, q.y, 0x5410), b0l = prmt(q.x, q.y, 0x7632);
            unsigned b1h = prmt(q.z, q.w, 0x5410), b1l = prmt(q.z, q.w, 0x7632);
            #pragma unroll
            for (int mt = 0; mt < 2; mt++) {
                mma16816(acc[mt][ni], ahi[mt], b0h, b1h);
                mma16816(acc[mt][ni], ahi[mt], b0l, b1l);
                mma16816(acc[mt][ni], alo[mt], b0h, b1h);
            }
        }
    }
    #pragma unroll
    for (int mt = 0; mt < 2; mt++) {
        int m = mb + mt * 16 + g;
        #pragma unroll
        for (int ni = 0; ni < 8; ni++) {
            int n = nb + ni * 8 + t * 2;
            float bx = bias[n], by = bias[n + 1];
            *(float2*)&out[(size_t)m * VV + n]       = make_float2(acc[mt][ni][0] + bx, acc[mt][ni][1] + by);
            *(float2*)&out[(size_t)(m + 8) * VV + n] = make_float2(acc[mt][ni][2] + bx, acc[mt][ni][3] + by);
        }
    }
}

// ---------------- launch ----------------
extern "C" void kernel_launch(void* const* d_in, const int* in_sizes, int n_in,
                              void* d_out, int out_size) {
    const int*   obs         = (const int*)d_in[0];
    const float* hidden_init = (const float*)d_in[1];
    const float* kci         = (const float*)d_in[2];
    const float* vci         = (const float*)d_in[3];
    const float* enc_w       = (const float*)d_in[4];
    const float* q_w         = (const float*)d_in[5];
    const float* q_b         = (const float*)d_in[6];
    const float* qn_g        = (const float*)d_in[7];
    const float* qn_b        = (const float*)d_in[8];
    const float* int_w       = (const float*)d_in[9];
    const float* int_b       = (const float*)d_in[10];
    const float* intn_g      = (const float*)d_in[11];
    const float* intn_b      = (const float*)d_in[12];
    const float* fin_w       = (const float*)d_in[13];
    const float* fin_b       = (const float*)d_in[14];
    const float* fn_g        = (const float*)d_in[15];
    const float* fn_b        = (const float*)d_in[16];
    const float* dec_w       = (const float*)d_in[17];
    const float* dec_b       = (const float*)d_in[18];

    float* out        = (float*)d_out;
    float* out_states = out + (size_t)SS * BB * VV;

    unsigned* qwp;  cudaGetSymbolAddress((void**)&qwp,  g_qwp);
    unsigned* iwp;  cudaGetSymbolAddress((void**)&iwp,  g_intwp);
    unsigned* fwp;  cudaGetSymbolAddress((void**)&fwp,  g_finwp);
    unsigned* dwp;  cudaGetSymbolAddress((void**)&dwp,  g_decwp);

    k_convert_frag<<<2048, 256>>>(q_w,   qwp, 1024 * 2048, 11);
    k_convert_frag<<<4096, 256>>>(int_w, iwp, 4096 * 4096, 12);
    k_convert_frag<<<4096, 256>>>(fin_w, fwp, 3072 * 4096, 12);
    k_convert_frag<<<4096, 256>>>(dec_w, dwp, VV * 1024, 10);

    k_embed<<<SS * BB, 256>>>(obs, enc_w);
    k_init<<<32, 256>>>(hidden_init, kci, vci, out_states);
    k_seq<<<NBLK, 512>>>(q_b, qn_g, qn_b, int_b, intn_g, intn_b,
                         fin_b, fn_g, fn_b, out_states);
    k_dec<<<dim3(4096 / 128, VV / 256), 512>>>(dec_b, out);
}

// round 6
// speedup vs baseline: 2.2300x; 1.0419x over previous
#include <cuda_runtime.h>
#include <cuda_bf16.h>
#include <math.h>

#define SS   128
#define BB   32
#define NINP 1024
#define NHID 1024
#define NH   16
#define HDIM 64
#define VV   32000
#define NBLK 148

// dynamic smem: W ping-pong 2x16384 u32 (128 KB) + A ping-pong 2x2048 u32 (16 KB)
#define SMEM_U32  36864
#define SMEM_BYTES (SMEM_U32 * 4)

// ---------------- scratch (device globals; no allocation) ----------------
__device__ float g_keys[(SS + 1) * BB * NHID];
__device__ float g_vals[(SS + 1) * BB * NHID];
__device__ float g_part[32 * BB * 1024];                       // 1M floats (4 MB)
__device__ unsigned g_cnt;
__device__ unsigned g_gen;

// fragment-ordered, PRE-SPLIT weights: per (n8,k16,lane) uint4 = (b0h,b1h,b0l,b1l)
__device__ __align__(16) unsigned g_qwp  [1024 * 2048];
__device__ __align__(16) unsigned g_intwp[4096 * 4096];
__device__ __align__(16) unsigned g_finwp[3072 * 4096];
__device__ __align__(16) unsigned g_decwp[VV * 1024];
// plain row-major packed (hi,lo in one u32) activations
__device__ __align__(16) unsigned g_embp [SS * BB * 1024];
__device__ __align__(16) unsigned g_hidp [BB * 1024];
__device__ __align__(16) unsigned g_qp   [BB * 1024];
__device__ __align__(16) unsigned g_attnp[BB * 1024];
__device__ __align__(16) unsigned g_interp[BB * 4096];
__device__ __align__(16) unsigned g_spack[SS * BB * 1024];

// ---------------- helpers ----------------
__device__ __forceinline__ unsigned packsplit(float x) {
    __nv_bfloat16 h = __float2bfloat16(x);
    __nv_bfloat16 l = __float2bfloat16(x - __bfloat162float(h));
    return (unsigned)__bfloat16_as_ushort(h) | ((unsigned)__bfloat16_as_ushort(l) << 16);
}
__device__ __forceinline__ unsigned prmt(unsigned a, unsigned b, unsigned s) {
    unsigned d; asm("prmt.b32 %0,%1,%2,%3;" : "=r"(d) : "r"(a), "r"(b), "r"(s)); return d;
}
__device__ __forceinline__ void mma16816(float* c, const unsigned* a, unsigned b0, unsigned b1) {
    asm volatile(
        "mma.sync.aligned.m16n8k16.row.col.f32.bf16.bf16.f32 "
        "{%0,%1,%2,%3}, {%4,%5,%6,%7}, {%8,%9}, {%0,%1,%2,%3};"
        : "+f"(c[0]), "+f"(c[1]), "+f"(c[2]), "+f"(c[3])
        : "r"(a[0]), "r"(a[1]), "r"(a[2]), "r"(a[3]), "r"(b0), "r"(b1));
}
__device__ __forceinline__ void cp16(unsigned dst, const void* src) {
    asm volatile("cp.async.cg.shared.global [%0], [%1], 16;" :: "r"(dst), "l"(src));
}
__device__ __forceinline__ void cp_commit() { asm volatile("cp.async.commit_group;"); }
template<int N_> __device__ __forceinline__ void cp_wait() {
    asm volatile("cp.async.wait_group %0;" :: "n"(N_));
}

// ---------------- grid barrier ----------------
__device__ __forceinline__ void gridbar() {
    __syncthreads();
    if (threadIdx.x == 0) {
        volatile unsigned* gen = &g_gen;
        unsigned g = *gen;
        __threadfence();
        if (atomicAdd(&g_cnt, 1u) == NBLK - 1) {
            g_cnt = 0;
            __threadfence();
            *gen = g + 1;
        } else {
            while (*gen == g) { __nanosleep(64); }
        }
        __threadfence();
    }
    __syncthreads();
}

struct SmemL { float buf[4096]; float red[32]; float qs[1024]; float sc[16][132]; };

__device__ __forceinline__ float block_reduce(float v, float* red) {
    __syncthreads();
    int tid = threadIdx.x;
    #pragma unroll
    for (int o = 16; o > 0; o >>= 1) v += __shfl_xor_sync(~0u, v, o);
    if ((tid & 31) == 0) red[tid >> 5] = v;
    __syncthreads();
    if (tid < 16) {
        v = red[tid];
        #pragma unroll
        for (int o = 8; o > 0; o >>= 1) v += __shfl_xor_sync(0xffff, v, o);
        if (tid == 0) red[0] = v;
    }
    __syncthreads();
    return red[0];
}

// ---------------- GEMM phase ----------------
__device__ __forceinline__ const uint4* stage_addr(const unsigned* const* segs, int segshift,
                                                   unsigned kmask, int xstride, int k0,
                                                   int sm_m, int sm_j) {
    const unsigned* seg = segs[k0 >> segshift];
    return (const uint4*)(seg + (size_t)sm_m * xstride + (k0 & kmask) + sm_j * 4);
}

// issue one 64-k W chunk (32 n8-tiles x 4 k16 x 32 lanes x 16B = 64 KB) via cp.async
__device__ __forceinline__ void issue_w(const unsigned* __restrict__ Wf, int K16tot,
                                        int n8_0, int k16_0, unsigned dst_smem) {
    const int tid = threadIdx.x;
    #pragma unroll
    for (int f = 0; f < 8; f++) {
        int id = f * 512 + tid;
        int kk = id >> 10, rest = id & 1023;
        const unsigned* src = Wf + (((size_t)(n8_0 + (rest >> 5)) * K16tot + k16_0 + kk) * 32
                                    + (rest & 31)) * 4;
        cp16(dst_smem + id * 16, src);
    }
    cp_commit();
}

// g_part[ks][32][N] = X[32 x K] @ W[N x K]^T on k-chunk ks. Block tile 32m x 256n,
// 16 warps each 32m x 16n. W cp.async double-buffered; A staged pre-split.
__device__ void gemm_mma(unsigned* dyn, const unsigned* const* segs, int segshift, int xstride,
                         const unsigned* __restrict__ Wf, int N, int K, int KS) {
    unsigned* Wbuf = dyn;              // 2 x 16384 u32
    unsigned* Abuf = dyn + 32768;      // 2 x 2048 u32
    const int ntasks = (N >> 8) * KS;
    const int Kc = K / KS;
    const int nc = Kc >> 6;
    const int K16tot = K >> 4;
    const unsigned kmask = (1u << segshift) - 1u;
    const int tid = threadIdx.x;
    const int warp = tid >> 5, lane = tid & 31;
    const int t = lane & 3, gq = lane >> 2;
    const unsigned wsm = (unsigned)__cvta_generic_to_shared(Wbuf);

    // A staging role
    const int sm_m = tid >> 4, sm_j = tid & 15;
    const int s_row = sm_m & 15, s_g = s_row & 7, s_rh = s_row >> 3, s_mt = sm_m >> 4;
    const int s_k16 = sm_j >> 2, s_kb = (sm_j & 3) << 2;
    const int s_t0 = (s_kb >> 1) & 3;
    const int s_w = s_rh + ((s_kb >> 3) << 1);
    const int s_base = ((s_k16 * 2 + s_mt) * 32 + s_g * 4 + s_t0) * 4 + s_w;

    int task = blockIdx.x;
    if (task >= ntasks) return;

    // prime: first chunk of first task
    uint4 v = *stage_addr(segs, segshift, kmask, xstride, (task % KS) * Kc, sm_m, sm_j);
    issue_w(Wf, K16tot, (task / KS) << 5, ((task % KS) * Kc) >> 4, wsm);
    int cc = 0;

    for (; task < ntasks; task += NBLK) {
        const int nt = task / KS, ks = task - nt * KS;
        const int n8_0 = nt << 5;
        const int k0b = ks * Kc;
        float acc[2][2][4];
        #pragma unroll
        for (int mt = 0; mt < 2; mt++)
            #pragma unroll
            for (int nti = 0; nti < 2; nti++)
                #pragma unroll
                for (int e = 0; e < 4; e++) acc[mt][nti][e] = 0.f;

        for (int c = 0; c < nc; c++) {
            const int p = cc & 1;
            unsigned* abuf = Abuf + p * 2048;
            // stage A (pre-split hi/lo fragments)
            abuf[s_base]            = prmt(v.x, v.y, 0x5410);
            abuf[s_base + 4]        = prmt(v.z, v.w, 0x5410);
            abuf[1024 + s_base]     = prmt(v.x, v.y, 0x7632);
            abuf[1024 + s_base + 4] = prmt(v.z, v.w, 0x7632);
            // prefetch next chunk (W via cp.async, A via regs)
            bool morechunk = (c + 1 < nc);
            bool moretask  = (task + NBLK < ntasks);
            if (morechunk) {
                issue_w(Wf, K16tot, n8_0, (k0b + (c + 1) * 64) >> 4, wsm + (p ^ 1) * 65536);
                v = *stage_addr(segs, segshift, kmask, xstride, k0b + (c + 1) * 64, sm_m, sm_j);
            } else if (moretask) {
                int t2 = task + NBLK;
                int nt2 = t2 / KS, ks2 = t2 - nt2 * KS;
                issue_w(Wf, K16tot, nt2 << 5, (ks2 * Kc) >> 4, wsm + (p ^ 1) * 65536);
                v = *stage_addr(segs, segshift, kmask, xstride, ks2 * Kc, sm_m, sm_j);
            }
            if (morechunk || moretask) cp_wait<1>(); else cp_wait<0>();
            __syncthreads();
            // consume chunk p
            const unsigned* wb = Wbuf + p * 16384;
            #pragma unroll
            for (int kk = 0; kk < 4; kk++) {
                unsigned ah[2][4], al[2][4];
                #pragma unroll
                for (int mt = 0; mt < 2; mt++) {
                    *(uint4*)ah[mt] = *(const uint4*)&abuf[((kk * 2 + mt) * 32 + lane) * 4];
                    *(uint4*)al[mt] = *(const uint4*)&abuf[1024 + ((kk * 2 + mt) * 32 + lane) * 4];
                }
                #pragma unroll
                for (int nti = 0; nti < 2; nti++) {
                    const uint4 q = *(const uint4*)&wb[((kk * 32 + warp * 2 + nti) * 32 + lane) * 4];
                    #pragma unroll
                    for (int mt = 0; mt < 2; mt++) {
                        mma16816(acc[mt][nti], ah[mt], q.x, q.y);   // hi*hi
                        mma16816(acc[mt][nti], ah[mt], q.z, q.w);   // hi*lo
                        mma16816(acc[mt][nti], al[mt], q.x, q.y);   // lo*hi
                    }
                }
            }
            __syncthreads();
            cc++;
        }
        float* dst = g_part + (size_t)ks * BB * N;
        const int n0w = (nt << 8) + (warp << 4);
        #pragma unroll
        for (int mt = 0; mt < 2; mt++) {
            int m = mt * 16 + gq;
            #pragma unroll
            for (int nti = 0; nti < 2; nti++) {
                int n = n0w + nti * 8 + t * 2;
                *(float2*)&dst[(size_t)m * N + n]       = make_float2(acc[mt][nti][0], acc[mt][nti][1]);
                *(float2*)&dst[(size_t)(m + 8) * N + n] = make_float2(acc[mt][nti][2], acc[mt][nti][3]);
            }
        }
    }
}

// ---------------- LN (+ReLU), sums KS partials + bias ----------------
__device__ void ln_phase(SmemL& sm, const float* __restrict__ bias, const float* __restrict__ gam,
                         const float* __restrict__ bet, int N, int KS, int mode, int i,
                         float* __restrict__ out_states) {
    int b = blockIdx.x;
    if (b >= BB) return;
    int tid = threadIdx.x;
    float s = 0.f, ss = 0.f;
    for (int j = tid; j < N; j += 512) {
        float v = bias[j];
        for (int ks = 0; ks < KS; ks++) v += g_part[(size_t)ks * BB * N + b * N + j];
        sm.buf[j] = v;
        s += v; ss += v * v;
    }
    float mu = block_reduce(s, sm.red) / (float)N;
    float var = block_reduce(ss, sm.red) / (float)N - mu * mu;
    float rs = rsqrtf(var + 1e-5f);
    for (int j = tid; j < N; j += 512) {
        float y = fmaxf((sm.buf[j] - mu) * rs * gam[j] + bet[j], 0.f);
        if (mode == 1) {
            g_interp[b * 4096 + j] = packsplit(y);
        } else {
            if (j < 1024)      g_keys[((size_t)(i + 1) * BB + b) * NHID + j] = y;
            else if (j < 2048) g_vals[((size_t)(i + 1) * BB + b) * NHID + (j - 1024)] = y;
            else {
                int jj = j - 2048;
                unsigned p = packsplit(y);
                g_hidp[b * 1024 + jj] = p;
                g_spack[((size_t)i * BB + b) * 1024 + jj] = p;
                out_states[((size_t)(i + 1) * BB + b) * NHID + jj] = y;
            }
        }
    }
}

// ---------------- fused LN(q) + attention ----------------
__device__ void ln_attn_phase(SmemL& sm, const float* __restrict__ bias, const float* __restrict__ gam,
                              const float* __restrict__ bet, int i) {
    int b = blockIdx.x;
    if (b >= BB) return;
    int tid = threadIdx.x;
    float s = 0.f, ss = 0.f;
    for (int j = tid; j < 1024; j += 512) {
        float v = bias[j];
        #pragma unroll
        for (int ks = 0; ks < 32; ks++) v += g_part[(size_t)ks * BB * 1024 + b * 1024 + j];
        sm.buf[j] = v;
        s += v; ss += v * v;
    }
    float mu = block_reduce(s, sm.red) / 1024.f;
    float var = block_reduce(ss, sm.red) / 1024.f - mu * mu;
    float rs = rsqrtf(var + 1e-5f);
    for (int j = tid; j < 1024; j += 512) {
        float y = fmaxf((sm.buf[j] - mu) * rs * gam[j] + bet[j], 0.f);
        sm.qs[j] = y;
        g_qp[b * 1024 + j] = packsplit(y);
    }
    __syncthreads();

    int len = i + 1;
    int hd = tid >> 5, lane = tid & 31;
    {
        float sv[4];
        float mx = -1e30f;
        #pragma unroll
        for (int r = 0; r < 4; r++) {
            int c = lane + 32 * r;
            float d = -1e30f;
            if (c < len) {
                const float* kp = g_keys + ((size_t)c * BB + b) * NHID + hd * HDIM;
                float a2 = 0.f;
                #pragma unroll
                for (int h = 0; h < HDIM; h += 4) {
                    float4 kv = *(const float4*)&kp[h];
                    a2 += kv.x * sm.qs[hd * HDIM + h]     + kv.y * sm.qs[hd * HDIM + h + 1]
                        + kv.z * sm.qs[hd * HDIM + h + 2] + kv.w * sm.qs[hd * HDIM + h + 3];
                }
                d = a2 * 0.125f;
            }
            sv[r] = d;
            mx = fmaxf(mx, d);
        }
        #pragma unroll
        for (int o = 16; o > 0; o >>= 1) mx = fmaxf(mx, __shfl_xor_sync(~0u, mx, o));
        float sum = 0.f;
        #pragma unroll
        for (int r = 0; r < 4; r++) {
            int c = lane + 32 * r;
            float e = (c < len) ? __expf(sv[r] - mx) : 0.f;
            sv[r] = e; sum += e;
        }
        #pragma unroll
        for (int o = 16; o > 0; o >>= 1) sum += __shfl_xor_sync(~0u, sum, o);
        float inv = 1.f / sum;
        #pragma unroll
        for (int r = 0; r < 4; r++) {
            int c = lane + 32 * r;
            if (c < len) sm.sc[hd][c] = sv[r] * inv;
        }
    }
    __syncthreads();

    for (int idx = tid; idx < 1024; idx += 512) {
        int h2 = idx >> 6, h = idx & 63;
        float a = 0.f;
        const float* vp = g_vals + b * NHID + h2 * HDIM + h;
        #pragma unroll 4
        for (int c = 0; c < len; c++) a += sm.sc[h2][c] * vp[(size_t)c * BB * NHID];
        g_attnp[b * 1024 + idx] = packsplit(a);
    }
}

// ---------------- persistent sequence kernel ----------------
__global__ void __launch_bounds__(512, 1) k_seq(
    const float* __restrict__ q_b,   const float* __restrict__ qn_g,  const float* __restrict__ qn_b,
    const float* __restrict__ int_b, const float* __restrict__ intn_g,const float* __restrict__ intn_b,
    const float* __restrict__ fin_b, const float* __restrict__ fn_g,  const float* __restrict__ fn_b,
    float* __restrict__ out_states)
{
    extern __shared__ __align__(16) unsigned dyn[];
    SmemL& sml = *reinterpret_cast<SmemL*>(dyn);
    for (int i = 0; i < SS; i++) {
        {   // GEMM1: [e|hidden] @ q_w^T  (N=1024, K=2048, KS=32 -> 128 tasks)
            const unsigned* segs[4] = { g_embp + (size_t)i * BB * 1024, g_hidp, g_hidp, g_hidp };
            gemm_mma(dyn, segs, 10, 1024, g_qwp, 1024, 2048, 32);
        }
        gridbar();
        ln_attn_phase(sml, q_b, qn_g, qn_b, i);
        gridbar();
        {   // GEMM2: [e|q|attn|hidden] @ int_w^T  (N=4096, K=4096, KS=8 -> 128 tasks)
            const unsigned* segs[4] = { g_embp + (size_t)i * BB * 1024, g_qp, g_attnp, g_hidp };
            gemm_mma(dyn, segs, 10, 1024, g_intwp, 4096, 4096, 8);
        }
        gridbar();
        ln_phase(sml, int_b, intn_g, intn_b, 4096, 8, 1, i, out_states);
        gridbar();
        {   // GEMM3: inter @ fin_w^T  (N=3072, K=4096, KS=8 -> 96 tasks)
            const unsigned* segs[4] = { g_interp, g_interp, g_interp, g_interp };
            gemm_mma(dyn, segs, 12, 4096, g_finwp, 3072, 4096, 8);
        }
        gridbar();
        ln_phase(sml, fin_b, fn_g, fn_b, 3072, 8, 2, i, out_states);
        gridbar();
    }
}

// ---------------- weight convert: split + pre-split fragment reorder ----------------
// output per (n8,k16,lane): uint4 = (b0h, b1h, b0l, b1l)
__global__ void k_convert_frag(const float* __restrict__ w, unsigned* __restrict__ wf,
                               int total, int kshift) {
    const int K = 1 << kshift;
    const int halfK = K >> 1;
    const int pairs = total >> 1;
    for (int i = blockIdx.x * 256 + threadIdx.x; i < pairs; i += gridDim.x * 256) {
        int kp = i & (halfK - 1);
        int n  = i >> (kshift - 1);
        int k  = kp << 1;
        unsigned p0 = packsplit(w[((size_t)n << kshift) + k]);
        unsigned p1 = packsplit(w[((size_t)n << kshift) + k + 1]);
        unsigned bh = prmt(p0, p1, 0x5410);
        unsigned bl = prmt(p0, p1, 0x7632);
        int n8 = n >> 3, g = n & 7;
        int k16 = k >> 4, kr = k & 15;
        int j = kr >> 1, t = j & 3, half = j >> 2;
        size_t base = (((size_t)n8 * (K >> 4) + k16) * 32 + g * 4 + t) * 4;
        wf[base + half]     = bh;
        wf[base + 2 + half] = bl;
    }
}

// ---------------- embedding gather (packed) ----------------
__global__ void k_embed(const int* __restrict__ obs, const float* __restrict__ enc_w) {
    int sb = blockIdx.x;
    int tok = obs[sb];
    const float4* src = (const float4*)(enc_w + (size_t)tok * NINP);
    float4 v = src[threadIdx.x];
    uint4 p = make_uint4(packsplit(v.x), packsplit(v.y), packsplit(v.z), packsplit(v.w));
    ((uint4*)(g_embp + (size_t)sb * NINP))[threadIdx.x] = p;
}

// ---------------- init ----------------
__global__ void k_init(const float* __restrict__ hidden_init,
                       const float* __restrict__ kci,
                       const float* __restrict__ vci,
                       float* __restrict__ out_states) {
    if (blockIdx.x == 0 && threadIdx.x == 0) { g_cnt = 0; g_gen = 0; }
    int idx = blockIdx.x * 256 + threadIdx.x;
    float4 h = ((const float4*)hidden_init)[idx];
    ((float4*)out_states)[idx] = h;
    ((float4*)g_keys)[idx] = ((const float4*)kci)[idx];
    ((float4*)g_vals)[idx] = ((const float4*)vci)[idx];
    uint4 p = make_uint4(packsplit(h.x), packsplit(h.y), packsplit(h.z), packsplit(h.w));
    ((uint4*)g_hidp)[idx] = p;
}

// ---------------- decoder: out[4096][32000] = states @ dec_w^T + dec_b ----------------
__global__ void __launch_bounds__(512, 1) k_dec(const float* __restrict__ bias,
                                                float* __restrict__ out) {
    const int m0 = blockIdx.x * 128;
    const int n0 = blockIdx.y * 256;
    const int warp = threadIdx.x >> 5, lane = threadIdx.x & 31;
    const int g = lane >> 2, t = lane & 3;
    const int mb = m0 + (warp & 3) * 32;
    const int nb = n0 + (warp >> 2) * 64;
    const int n8b = nb >> 3;

    float acc[2][8][4];
    #pragma unroll
    for (int mt = 0; mt < 2; mt++)
        #pragma unroll
        for (int ni = 0; ni < 8; ni++)
            #pragma unroll
            for (int e = 0; e < 4; e++) acc[mt][ni][e] = 0.f;

    for (int k0 = 0; k0 < 1024; k0 += 16) {
        unsigned ahi[2][4], alo[2][4];
        #pragma unroll
        for (int mt = 0; mt < 2; mt++) {
            const unsigned* x0 = g_spack + (size_t)(mb + mt * 16 + g) * 1024 + k0 + t * 2;
            const unsigned* x8 = x0 + 8 * 1024;
            uint2 p0 = *(const uint2*)x0;
            uint2 p1 = *(const uint2*)x8;
            uint2 p2 = *(const uint2*)(x0 + 8);
            uint2 p3 = *(const uint2*)(x8 + 8);
            ahi[mt][0] = prmt(p0.x, p0.y, 0x5410); alo[mt][0] = prmt(p0.x, p0.y, 0x7632);
            ahi[mt][1] = prmt(p1.x, p1.y, 0x5410); alo[mt][1] = prmt(p1.x, p1.y, 0x7632);
            ahi[mt][2] = prmt(p2.x, p2.y, 0x5410); alo[mt][2] = prmt(p2.x, p2.y, 0x7632);
            ahi[mt][3] = prmt(p3.x, p3.y, 0x5410); alo[mt][3] = prmt(p3.x, p3.y, 0x7632);
        }
        #pragma unroll
        for (int ni = 0; ni < 8; ni++) {
            const uint4 q = *(const uint4*)(g_decwp + (((size_t)(n8b + ni) * 64 + (k0 >> 4)) * 32 + lane) * 4);
            #pragma unroll
            for (int mt = 0; mt < 2; mt++) {
                mma16816(acc[mt][ni], ahi[mt], q.x, q.y);
                mma16816(acc[mt][ni], ahi[mt], q.z, q.w);
                mma16816(acc[mt][ni], alo[mt], q.x, q.y);
            }
        }
    }
    #pragma unroll
    for (int mt = 0; mt < 2; mt++) {
        int m = mb + mt * 16 + g;
        #pragma unroll
        for (int ni = 0; ni < 8; ni++) {
            int n = nb + ni * 8 + t * 2;
            float bx = bias[n], by = bias[n + 1];
            *(float2*)&out[(size_t)m * VV + n]       = make_float2(acc[mt][ni][0] + bx, acc[mt][ni][1] + by);
            *(float2*)&out[(size_t)(m + 8) * VV + n] = make_float2(acc[mt][ni][2] + bx, acc[mt][ni][3] + by);
        }
    }
}

// ---------------- launch ----------------
extern "C" void kernel_launch(void* const* d_in, const int* in_sizes, int n_in,
                              void* d_out, int out_size) {
    const int*   obs         = (const int*)d_in[0];
    const float* hidden_init = (const float*)d_in[1];
    const float* kci         = (const float*)d_in[2];
    const float* vci         = (const float*)d_in[3];
    const float* enc_w       = (const float*)d_in[4];
    const float* q_w         = (const float*)d_in[5];
    const float* q_b         = (const float*)d_in[6];
    const float* qn_g        = (const float*)d_in[7];
    const float* qn_b        = (const float*)d_in[8];
    const float* int_w       = (const float*)d_in[9];
    const float* int_b       = (const float*)d_in[10];
    const float* intn_g      = (const float*)d_in[11];
    const float* intn_b      = (const float*)d_in[12];
    const float* fin_w       = (const float*)d_in[13];
    const float* fin_b       = (const float*)d_in[14];
    const float* fn_g        = (const float*)d_in[15];
    const float* fn_b        = (const float*)d_in[16];
    const float* dec_w       = (const float*)d_in[17];
    const float* dec_b       = (const float*)d_in[18];

    float* out        = (float*)d_out;
    float* out_states = out + (size_t)SS * BB * VV;

    unsigned* qwp;  cudaGetSymbolAddress((void**)&qwp,  g_qwp);
    unsigned* iwp;  cudaGetSymbolAddress((void**)&iwp,  g_intwp);
    unsigned* fwp;  cudaGetSymbolAddress((void**)&fwp,  g_finwp);
    unsigned* dwp;  cudaGetSymbolAddress((void**)&dwp,  g_decwp);

    static int smem_set = 0;
    if (!smem_set) {
        cudaFuncSetAttribute(k_seq, cudaFuncAttributeMaxDynamicSharedMemorySize, SMEM_BYTES);
        smem_set = 1;
    }

    k_convert_frag<<<2048, 256>>>(q_w,   qwp, 1024 * 2048, 11);
    k_convert_frag<<<4096, 256>>>(int_w, iwp, 4096 * 4096, 12);
    k_convert_frag<<<4096, 256>>>(fin_w, fwp, 3072 * 4096, 12);
    k_convert_frag<<<4096, 256>>>(dec_w, dwp, VV * 1024, 10);

    k_embed<<<SS * BB, 256>>>(obs, enc_w);
    k_init<<<32, 256>>>(hidden_init, kci, vci, out_states);
    k_seq<<<NBLK, 512, SMEM_BYTES>>>(q_b, qn_g, qn_b, int_b, intn_g, intn_b,
                                     fin_b, fn_g, fn_b, out_states);
    k_dec<<<dim3(4096 / 128, VV / 256), 512>>>(dec_b, out);
}